// round 11
// baseline (speedup 1.0000x reference)
#include <cuda_runtime.h>
#include <cuda_fp16.h>

#define N_NODES 12288
#define DIM 64
#define N_EDGES 262144
#define EPS_F 0.01f
#define BLK 512
#define GRID_BLOCKS 444   // ~3 blocks/SM on 148 SMs

// Repacked storage: r rows compressed to fp16 (64 halfs = 128B = ONE cache
// line per row), m kept fp32.
__device__ __half g_rh[N_NODES * DIM];
__device__ float  g_m[N_NODES];

// Pre-pass, 4 elements per thread: 4 independent coalesced LDG.32 (MLP=4)
// + one vectorized 8-byte store of 4 halfs. 196608 threads total.
__global__ void __launch_bounds__(256) repack_kernel(const float* __restrict__ z) {
    int t = blockIdx.x * blockDim.x + threadIdx.x;
    const int quads = N_NODES * DIM / 4;   // 196608
    if (t < quads) {
        int row = t >> 4;          // 16 quads per 64-wide row
        int col = (t & 15) << 2;
        const float* src = z + row * 65 + col;
        float x0 = src[0];
        float x1 = src[1];
        float x2 = src[2];
        float x3 = src[3];
        __half2 h0 = __floats2half2_rn(x0, x1);
        __half2 h1 = __floats2half2_rn(x2, x3);
        uint2 w;
        w.x = *reinterpret_cast<unsigned*>(&h0);
        w.y = *reinterpret_cast<unsigned*>(&h1);
        *reinterpret_cast<uint2*>(g_rh + (size_t)t * 4) = w;
    }
    if (t < N_NODES) {
        g_m[t] = z[t * 65 + 64];
    }
}

// Accumulate ||a-b||^2 contribution of one 16B chunk (8 halfs), fp32 math
// (proven R8 inner-loop form: convert both operands, subtract in fp32).
__device__ __forceinline__ float sq_chunk(const uint4& pa, const uint4& pb) {
    const __half2* ha = reinterpret_cast<const __half2*>(&pa);
    const __half2* hb = reinterpret_cast<const __half2*>(&pb);
    float acc = 0.0f;
    #pragma unroll
    for (int k = 0; k < 4; k++) {
        float2 fa = __half22float2(ha[k]);
        float2 fb = __half22float2(hb[k]);
        float dx = fa.x - fb.x;
        float dy = fa.y - fb.y;
        acc = fmaf(dx, dx, acc);
        acc = fmaf(dy, dy, acc);
    }
    return acc;
}

// Persistent blocks: each block stages the full m array (48KB) in shared
// memory once, then grid-strides over edge pairs. Per-edge m access becomes
// an LDS -> the ~2 random L1tex wavefronts/edge for m gathers disappear.
// 8 lanes per group, 2 edges per group-iteration; u0/u1 and v0/v1 are
// consecutive, so index loads merge into two LDG.64.
__global__ void __launch_bounds__(BLK) edge_kernel(
        const int* __restrict__ eidx,
        const float* __restrict__ lptr,
        float4* __restrict__ out) {
    __shared__ float s_m[N_NODES];

    // Stage m: 12288 floats = 3072 float4, 512 threads x 6 each (coalesced).
    {
        const float4* gm4 = reinterpret_cast<const float4*>(g_m);
        float4* sm4 = reinterpret_cast<float4*>(s_m);
        #pragma unroll
        for (int t = threadIdx.x; t < N_NODES / 4; t += BLK)
            sm4[t] = gm4[t];
    }
    __syncthreads();

    const unsigned lane_grp = threadIdx.x & 7u;           // lane within group
    const unsigned group    = (blockIdx.x * (BLK / 8)) + (threadIdx.x >> 3);
    const unsigned ngroups  = gridDim.x * (BLK / 8);
    const float l = __ldg(lptr);
    const uint4* __restrict__ rb = reinterpret_cast<const uint4*>(g_rh);

    for (unsigned p = group; p < N_EDGES / 2; p += ngroups) {
        unsigned e0 = 2u * p;
        unsigned e1 = e0 + 1u;

        // Merged index loads: one LDG.64 for (u0,u1), one for (v0,v1).
        int2 uu = *reinterpret_cast<const int2*>(eidx + e0);
        int2 vv = *reinterpret_cast<const int2*>(eidx + N_EDGES + e0);
        int u0 = uu.x, u1 = uu.y;
        int v0 = vv.x, v1 = vv.y;

        // Payload: 4 independent LDG.128 (one full 128B row each).
        uint4 pa0 = rb[u0 * 8 + lane_grp];
        uint4 pb0 = rb[v0 * 8 + lane_grp];
        uint4 pa1 = rb[u1 * 8 + lane_grp];
        uint4 pb1 = rb[v1 * 8 + lane_grp];

        // m from shared memory (no L1tex wavefronts).
        float m_u0 = s_m[u0];
        float m_v0 = s_m[v0];
        float m_u1 = s_m[u1];
        float m_v1 = s_m[v1];

        float acc0 = sq_chunk(pa0, pb0);
        float acc1 = sq_chunk(pa1, pb1);

        acc0 += __shfl_xor_sync(0xffffffffu, acc0, 4);
        acc1 += __shfl_xor_sync(0xffffffffu, acc1, 4);
        acc0 += __shfl_xor_sync(0xffffffffu, acc0, 2);
        acc1 += __shfl_xor_sync(0xffffffffu, acc1, 2);
        acc0 += __shfl_xor_sync(0xffffffffu, acc0, 1);
        acc1 += __shfl_xor_sync(0xffffffffu, acc1, 1);

        if (lane_grp == 0) {
            float lg0 = __logf(acc0 + EPS_F);
            float lg1 = __logf(acc1 + EPS_F);
            float luv0 = fmaf(-l, lg0, m_v0);
            float lvu0 = fmaf(-l, lg0, m_u0);
            float luv1 = fmaf(-l, lg1, m_v1);
            float lvu1 = fmaf(-l, lg1, m_u1);
            float suv0 = __fdividef(1.0f, 1.0f + __expf(-luv0));
            float svu0 = __fdividef(1.0f, 1.0f + __expf(-lvu0));
            float suv1 = __fdividef(1.0f, 1.0f + __expf(-luv1));
            float svu1 = __fdividef(1.0f, 1.0f + __expf(-lvu1));
            float4 o0, o1;
            o0.x = (1.0f - suv0) * (1.0f - svu0);
            o0.y = suv0 * (1.0f - svu0);
            o0.z = suv0 * svu0;
            o0.w = (1.0f - suv0) * svu0;
            o1.x = (1.0f - suv1) * (1.0f - svu1);
            o1.y = suv1 * (1.0f - svu1);
            o1.z = suv1 * svu1;
            o1.w = (1.0f - suv1) * svu1;
            out[e0] = o0;
            out[e1] = o1;
        }
    }
}

extern "C" void kernel_launch(void* const* d_in, const int* in_sizes, int n_in,
                              void* d_out, int out_size) {
    const float* z    = (const float*)d_in[0];
    const float* l    = (const float*)d_in[1];
    const int*   eidx = (const int*)d_in[2];   // int64 in reference, but JAX
                                               // x64 is disabled -> int32
    float4*      out  = (float4*)d_out;

    // Repack: 196608 threads (4 elements each)
    {
        int threads = 256;
        int quads = N_NODES * DIM / 4;
        int blocks = (quads + threads - 1) / threads;
        repack_kernel<<<blocks, threads>>>(z);
    }

    // Persistent edge kernel.
    edge_kernel<<<GRID_BLOCKS, BLK>>>(eidx, l, out);
}

// round 12
// speedup vs baseline: 1.0453x; 1.0453x over previous
#include <cuda_runtime.h>
#include <cuda_fp16.h>

#define N_NODES 12288
#define DIM 64
#define N_EDGES 262144
#define EPS_F 0.01f

// Repacked storage: r rows compressed to fp16 (64 halfs = 128B = ONE cache
// line per row); per-edge m pairs gathered once in the pre-pass.
__device__ __half g_rh[N_NODES * DIM];
__device__ float2 g_me[N_EDGES];   // {m_u, m_v} per edge, coalesced for edge kernel

// Pre-pass, 262144 threads:
//  - t < 196608: repack 4 r-elements to fp16 (4 coalesced LDG + 1 STG.64)
//  - all t:      gather this edge's (m_u, m_v) from z and store coalesced.
// The random m gathers live HERE (latency-slack kernel), not in the hot one.
__global__ void __launch_bounds__(256) repack_kernel(
        const float* __restrict__ z,
        const int* __restrict__ eidx) {
    int t = blockIdx.x * blockDim.x + threadIdx.x;
    const int quads = N_NODES * DIM / 4;   // 196608

    // Per-edge m gather (all threads: t == edge id)
    if (t < N_EDGES) {
        int u = eidx[t];
        int v = eidx[N_EDGES + t];
        float mu = z[u * 65 + 64];
        float mv = z[v * 65 + 64];
        g_me[t] = make_float2(mu, mv);
    }

    if (t < quads) {
        int row = t >> 4;          // 16 quads per 64-wide row
        int col = (t & 15) << 2;
        const float* src = z + row * 65 + col;
        float x0 = src[0];
        float x1 = src[1];
        float x2 = src[2];
        float x3 = src[3];
        __half2 h0 = __floats2half2_rn(x0, x1);
        __half2 h1 = __floats2half2_rn(x2, x3);
        uint2 w;
        w.x = *reinterpret_cast<unsigned*>(&h0);
        w.y = *reinterpret_cast<unsigned*>(&h1);
        *reinterpret_cast<uint2*>(g_rh + (size_t)t * 4) = w;
    }
}

// Accumulate ||a-b||^2 contribution of one 16B chunk (8 halfs), fp32 math
// (proven R8 inner-loop form: convert both operands, subtract in fp32).
__device__ __forceinline__ float sq_chunk(const uint4& pa, const uint4& pb) {
    const __half2* ha = reinterpret_cast<const __half2*>(&pa);
    const __half2* hb = reinterpret_cast<const __half2*>(&pb);
    float acc = 0.0f;
    #pragma unroll
    for (int k = 0; k < 4; k++) {
        float2 fa = __half22float2(ha[k]);
        float2 fb = __half22float2(hb[k]);
        float dx = fa.x - fb.x;
        float dy = fa.y - fb.y;
        acc = fmaf(dx, dx, acc);
        acc = fmaf(dy, dy, acc);
    }
    return acc;
}

// 8 lanes per group, 2 edges per thread (R6 chassis). fp16 rows: one
// LDG.128 wavefront per row. m arrives as ONE coalesced float4 per thread
// (both edges' {m_u, m_v}) instead of 4 random scalar gathers.
__global__ void __launch_bounds__(256) edge_kernel(
        const int* __restrict__ eidx,
        const float* __restrict__ lptr,
        float4* __restrict__ out) {
    unsigned tid = blockIdx.x * blockDim.x + threadIdx.x;
    unsigned g = tid >> 3;            // group id: handles edges 2g, 2g+1
    unsigned i = tid & 7u;
    unsigned e0 = 2u * g;
    if (e0 >= N_EDGES) return;
    unsigned e1 = e0 + 1u;

    // Merged index loads (LDG.64) + coalesced m-pair load (LDG.128).
    int2 uu = *reinterpret_cast<const int2*>(eidx + e0);
    int2 vv = *reinterpret_cast<const int2*>(eidx + N_EDGES + e0);
    float4 mm = *reinterpret_cast<const float4*>(g_me + e0);
    // mm = {m_u0, m_v0, m_u1, m_v1}

    const uint4* __restrict__ rb = reinterpret_cast<const uint4*>(g_rh);

    // Payload: 4 independent LDG.128 (one full 128B row each).
    uint4 pa0 = rb[uu.x * 8 + i];
    uint4 pb0 = rb[vv.x * 8 + i];
    uint4 pa1 = rb[uu.y * 8 + i];
    uint4 pb1 = rb[vv.y * 8 + i];

    float acc0 = sq_chunk(pa0, pb0);
    float acc1 = sq_chunk(pa1, pb1);

    // Interleaved 3-step reduces across the 8-lane group.
    acc0 += __shfl_xor_sync(0xffffffffu, acc0, 4);
    acc1 += __shfl_xor_sync(0xffffffffu, acc1, 4);
    acc0 += __shfl_xor_sync(0xffffffffu, acc0, 2);
    acc1 += __shfl_xor_sync(0xffffffffu, acc1, 2);
    acc0 += __shfl_xor_sync(0xffffffffu, acc0, 1);
    acc1 += __shfl_xor_sync(0xffffffffu, acc1, 1);

    if (i == 0) {
        float l   = __ldg(lptr);
        float lg0 = __logf(acc0 + EPS_F);
        float lg1 = __logf(acc1 + EPS_F);

        float luv0 = fmaf(-l, lg0, mm.y);   // m_v0
        float lvu0 = fmaf(-l, lg0, mm.x);   // m_u0
        float luv1 = fmaf(-l, lg1, mm.w);   // m_v1
        float lvu1 = fmaf(-l, lg1, mm.z);   // m_u1

        float suv0 = __fdividef(1.0f, 1.0f + __expf(-luv0));
        float svu0 = __fdividef(1.0f, 1.0f + __expf(-lvu0));
        float suv1 = __fdividef(1.0f, 1.0f + __expf(-luv1));
        float svu1 = __fdividef(1.0f, 1.0f + __expf(-lvu1));

        float4 o0, o1;
        o0.x = (1.0f - suv0) * (1.0f - svu0);
        o0.y = suv0 * (1.0f - svu0);
        o0.z = suv0 * svu0;
        o0.w = (1.0f - suv0) * svu0;
        o1.x = (1.0f - suv1) * (1.0f - svu1);
        o1.y = suv1 * (1.0f - svu1);
        o1.z = suv1 * svu1;
        o1.w = (1.0f - suv1) * svu1;
        out[e0] = o0;
        out[e1] = o1;
    }
}

extern "C" void kernel_launch(void* const* d_in, const int* in_sizes, int n_in,
                              void* d_out, int out_size) {
    const float* z    = (const float*)d_in[0];
    const float* l    = (const float*)d_in[1];
    const int*   eidx = (const int*)d_in[2];   // int64 in reference, but JAX
                                               // x64 is disabled -> int32
    float4*      out  = (float4*)d_out;

    // Repack + per-edge m gather: 262144 threads
    {
        int threads = 256;
        int blocks = (N_EDGES + threads - 1) / threads;
        repack_kernel<<<blocks, threads>>>(z, eidx);
    }

    // Edge kernel: 8 threads per 2 edges -> N_EDGES*4 = 1,048,576 threads
    {
        int threads = 256;
        long long total = (long long)N_EDGES * 4;
        int blocks = (int)((total + threads - 1) / threads);
        edge_kernel<<<blocks, threads>>>(eidx, l, out);
    }
}